// round 11
// baseline (speedup 1.0000x reference)
#include <cuda_runtime.h>
#include <stdint.h>

// StridedSlice: out[n,c,h,w] = x[n,c,2h,2w]
//   in : (8,128,512,512) f32   in row = 128 float4, plane = 65536 float4
//   out: (8,128,256,256) f32   out row = 64 float4, 262144 rows total
//
// TMA-bulk-store variant. Each block (256 thr) produces 16 consecutive
// output rows (16 KB, contiguous in gmem). Warps load with LDG.256 at
// 32 B lane stride (sector-exact, proven pattern), decimate, stage into
// SMEM in linear output layout (conflict-free STS.128, lane stride 16 B),
// then ONE cp.async.bulk (shared->global, 16 KB) per block writes out as
// a single coarse burst via the TMA engine — decoupling the write stream
// from load issue and coarsening DRAM write bursts.

__device__ __forceinline__ void ldg256(const float4* __restrict__ p,
                                       float4& v0, float4& v1)
{
    asm volatile("ld.global.v8.f32 {%0,%1,%2,%3,%4,%5,%6,%7}, [%8];"
                 : "=f"(v0.x), "=f"(v0.y), "=f"(v0.z), "=f"(v0.w),
                   "=f"(v1.x), "=f"(v1.y), "=f"(v1.z), "=f"(v1.w)
                 : "l"(p));
}

__global__ __launch_bounds__(256) void strided_slice_kernel(
    const float4* __restrict__ in, float4* __restrict__ out)
{
    __shared__ __align__(128) float4 tile[1024];   // 16 KB staging

    unsigned tid = threadIdx.x;
    unsigned w   = tid >> 5;        // warp 0..7
    unsigned t   = tid & 31u;

    unsigned R  = blockIdx.x << 4;  // first of 16 output rows for this block
    unsigned h  = R & 255u;         // multiple of 16; all rows in one plane
    unsigned nc = R >> 8;

    const float4* __restrict__ ib = in + ((size_t)nc << 16) + ((size_t)h << 8);

    unsigned j0 = w << 1;           // this warp's 2 local rows: j0, j0+1
    unsigned t2 = t << 1;

    // ---- load + decimate + stage (front-batched LDG.256) ----
    const float4* p0 = ib + j0 * 256;          // input row 2(h+j0)
    float4 a0, a1, a2, a3, b0, b1, b2, b3;
    ldg256(p0 + t2,        a0, a1);            // row j0,   out cols 0..31
    ldg256(p0 + t2 + 64,   a2, a3);            // row j0,   out cols 32..63
    ldg256(p0 + t2 + 256,  b0, b1);            // row j0+1, out cols 0..31
    ldg256(p0 + t2 + 320,  b2, b3);            // row j0+1, out cols 32..63

    float4* s = tile + j0 * 64;                // linear output layout in smem
    s[t]       = make_float4(a0.x, a0.z, a1.x, a1.z);
    s[32 + t]  = make_float4(a2.x, a2.z, a3.x, a3.z);
    s[64 + t]  = make_float4(b0.x, b0.z, b1.x, b1.z);
    s[96 + t]  = make_float4(b2.x, b2.z, b3.x, b3.z);

    __syncthreads();

    // ---- single 16 KB bulk store for the whole block ----
    if (tid == 0) {
        uint32_t saddr;
        asm("{ .reg .u64 x; cvta.to.shared.u64 x, %1; cvt.u32.u64 %0, x; }"
            : "=r"(saddr) : "l"(tile));
        const float4* g = out + ((size_t)R << 6);
        asm volatile("fence.proxy.async.shared::cta;" ::: "memory");
        asm volatile("cp.async.bulk.global.shared::cta.bulk_group [%0], [%1], 16384;"
                     :: "l"(g), "r"(saddr) : "memory");
        asm volatile("cp.async.bulk.commit_group;" ::: "memory");
        // release SMEM as soon as TMA has READ it (don't wait for write landing)
        asm volatile("cp.async.bulk.wait_group.read 0;" ::: "memory");
    }
    __syncthreads();   // no thread exits before SMEM is safe to retire
}

extern "C" void kernel_launch(void* const* d_in, const int* in_sizes, int n_in,
                              void* d_out, int out_size)
{
    (void)in_sizes; (void)n_in; (void)out_size;
    const float4* in  = (const float4*)d_in[0];
    float4*       out = (float4*)d_out;

    // 262144 output rows / 16 rows per block = 16384 blocks of 256 threads
    strided_slice_kernel<<<16384, 256>>>(in, out);
}

// round 12
// speedup vs baseline: 1.0011x; 1.0011x over previous
#include <cuda_runtime.h>
#include <stdint.h>

// StridedSlice: out[n,c,h,w] = x[n,c,2h,2w]
//   in : (8,128,512,512) f32   in row = 128 float4, plane = 65536 float4
//   out: (8,128,256,256) f32   out row = 64 float4, 262144 rows total
//
// TMA-bulk-store, 32 KB tiles. Each block (512 thr, 16 warps) produces 32
// consecutive output rows (32 KB contiguous in gmem). Each warp handles 2
// rows with the proven sector-exact LDG.256 pattern (32 B lane stride),
// decimates, stages into SMEM in linear output layout, then ONE
// cp.async.bulk (shared->global, 32 KB) per block drains the write stream
// as a long sequential burst via the TMA engine — decoupled from load issue.

__device__ __forceinline__ void ldg256(const float4* __restrict__ p,
                                       float4& v0, float4& v1)
{
    asm volatile("ld.global.v8.f32 {%0,%1,%2,%3,%4,%5,%6,%7}, [%8];"
                 : "=f"(v0.x), "=f"(v0.y), "=f"(v0.z), "=f"(v0.w),
                   "=f"(v1.x), "=f"(v1.y), "=f"(v1.z), "=f"(v1.w)
                 : "l"(p));
}

__global__ __launch_bounds__(512) void strided_slice_kernel(
    const float4* __restrict__ in, float4* __restrict__ out)
{
    __shared__ __align__(128) float4 tile[2048];   // 32 KB staging

    unsigned tid = threadIdx.x;
    unsigned w   = tid >> 5;        // warp 0..15
    unsigned t   = tid & 31u;

    unsigned R  = blockIdx.x << 5;  // first of 32 output rows for this block
    unsigned h  = R & 255u;         // multiple of 32; all rows in one plane
    unsigned nc = R >> 8;

    const float4* __restrict__ ib = in + ((size_t)nc << 16) + ((size_t)h << 8);

    unsigned j0 = w << 1;           // this warp's 2 local rows: j0, j0+1
    unsigned t2 = t << 1;

    // ---- load + decimate + stage (front-batched LDG.256) ----
    const float4* p0 = ib + j0 * 256;          // input row 2(h+j0)
    float4 a0, a1, a2, a3, b0, b1, b2, b3;
    ldg256(p0 + t2,        a0, a1);            // row j0,   out cols 0..31
    ldg256(p0 + t2 + 64,   a2, a3);            // row j0,   out cols 32..63
    ldg256(p0 + t2 + 256,  b0, b1);            // row j0+1, out cols 0..31
    ldg256(p0 + t2 + 320,  b2, b3);            // row j0+1, out cols 32..63

    float4* s = tile + j0 * 64;                // linear output layout in smem
    s[t]       = make_float4(a0.x, a0.z, a1.x, a1.z);
    s[32 + t]  = make_float4(a2.x, a2.z, a3.x, a3.z);
    s[64 + t]  = make_float4(b0.x, b0.z, b1.x, b1.z);
    s[96 + t]  = make_float4(b2.x, b2.z, b3.x, b3.z);

    __syncthreads();

    // ---- single 32 KB bulk store for the whole block ----
    if (tid == 0) {
        uint32_t saddr;
        asm("{ .reg .u64 x; cvta.to.shared.u64 x, %1; cvt.u32.u64 %0, x; }"
            : "=r"(saddr) : "l"(tile));
        const float4* g = out + ((size_t)R << 6);
        asm volatile("fence.proxy.async.shared::cta;" ::: "memory");
        asm volatile("cp.async.bulk.global.shared::cta.bulk_group [%0], [%1], 32768;"
                     :: "l"(g), "r"(saddr) : "memory");
        asm volatile("cp.async.bulk.commit_group;" ::: "memory");
        // release SMEM as soon as TMA has READ it (don't wait for write landing)
        asm volatile("cp.async.bulk.wait_group.read 0;" ::: "memory");
    }
    __syncthreads();   // no thread exits before SMEM is safe to retire
}

extern "C" void kernel_launch(void* const* d_in, const int* in_sizes, int n_in,
                              void* d_out, int out_size)
{
    (void)in_sizes; (void)n_in; (void)out_size;
    const float4* in  = (const float4*)d_in[0];
    float4*       out = (float4*)d_out;

    // 262144 output rows / 32 rows per block = 8192 blocks of 512 threads
    strided_slice_kernel<<<8192, 512>>>(in, out);
}